// round 1
// baseline (speedup 1.0000x reference)
#include <cuda_runtime.h>
#include <math.h>

// ---------------------------------------------------------------------------
// MoE FFN + residual + LayerNorm, fused-pipeline fp32 baseline.
// T=8192 tokens, D=1024, H=2048, E=8 experts, top-2.
// ---------------------------------------------------------------------------

constexpr int T_TOK = 8192;
constexpr int D_IN  = 1024;
constexpr int D_HID = 2048;
constexpr int NEXP  = 8;

constexpr int BM = 128;                         // GEMM row tile
constexpr int MAX_ROWS  = T_TOK * 2 + NEXP * BM; // 17408 (padded segments)
constexpr int MAX_TILES = MAX_ROWS / BM;         // 136

// ------------------------- device scratch (static) -------------------------
__device__ float g_h[(size_t)MAX_ROWS * D_HID];   // GEMM1 output (relu(xW1+b1))
__device__ float g_yb[(size_t)MAX_ROWS * D_IN];   // GEMM2 output (hW2+b2)
__device__ int   g_row_token[MAX_ROWS];           // padded row -> token (-1 pad)
__device__ int   g_pos_of[T_TOK * 2];             // (token,slot) -> padded row
__device__ int   g_sel[T_TOK * 2];                // (token,slot) -> expert
__device__ float g_gate[T_TOK * 2];               // (token,slot) -> gate
__device__ int   g_counts[NEXP];
__device__ int   g_cursors[NEXP];
__device__ int   g_tile_expert[MAX_TILES];
__device__ int   g_n_tiles;

// ------------------------------ init --------------------------------------
__global__ void k_init() {
    int i = blockIdx.x * blockDim.x + threadIdx.x;
    if (i < MAX_ROWS) g_row_token[i] = -1;
    if (i < NEXP) g_counts[i] = 0;
}

// ------------------------------ gating ------------------------------------
// 1 warp per token: logits = x[t] @ Wg, top-2, softmax.
__global__ void k_gate(const float* __restrict__ x, const float* __restrict__ Wg) {
    int warp = threadIdx.x >> 5;
    int lane = threadIdx.x & 31;
    int t = blockIdx.x * 8 + warp;
    if (t >= T_TOK) return;
    const float* xr = x + (size_t)t * D_IN;
    const float4* wg4 = reinterpret_cast<const float4*>(Wg);

    float acc[8];
#pragma unroll
    for (int j = 0; j < 8; j++) acc[j] = 0.f;

    for (int i = lane; i < D_IN; i += 32) {
        float xv = xr[i];
        float4 a = wg4[i * 2];
        float4 b = wg4[i * 2 + 1];
        acc[0] += xv * a.x; acc[1] += xv * a.y; acc[2] += xv * a.z; acc[3] += xv * a.w;
        acc[4] += xv * b.x; acc[5] += xv * b.y; acc[6] += xv * b.z; acc[7] += xv * b.w;
    }
#pragma unroll
    for (int j = 0; j < 8; j++) {
#pragma unroll
        for (int off = 16; off; off >>= 1)
            acc[j] += __shfl_down_sync(0xffffffff, acc[j], off);
    }
    if (lane == 0) {
        int i0 = 0; float v0 = acc[0];
#pragma unroll
        for (int e = 1; e < 8; e++) if (acc[e] > v0) { v0 = acc[e]; i0 = e; }
        int i1 = -1; float v1 = -3.4e38f;
#pragma unroll
        for (int e = 0; e < 8; e++)
            if (e != i0 && acc[e] > v1) { v1 = acc[e]; i1 = e; }
        float e1 = expf(v1 - v0);          // v0 >= v1
        float inv = 1.f / (1.f + e1);
        float g0 = inv;
        float g1 = e1 * inv;
        g_sel[2 * t]     = i0;  g_sel[2 * t + 1]  = i1;
        g_gate[2 * t]    = g0;  g_gate[2 * t + 1] = g1;
        atomicAdd(&g_counts[i0], 1);
        atomicAdd(&g_counts[i1], 1);
    }
}

// ------------------------------ scan ---------------------------------------
__global__ void k_scan() {
    int total_tiles = 0, pos = 0;
    for (int e = 0; e < NEXP; e++) {
        g_cursors[e] = pos;
        int nt = (g_counts[e] + BM - 1) / BM;
        for (int j = 0; j < nt; j++) g_tile_expert[total_tiles + j] = e;
        total_tiles += nt;
        pos += nt * BM;
    }
    g_n_tiles = total_tiles;
}

// ------------------------------ scatter -------------------------------------
__global__ void k_scatter() {
    int t = blockIdx.x * blockDim.x + threadIdx.x;
    if (t >= T_TOK) return;
#pragma unroll
    for (int slot = 0; slot < 2; slot++) {
        int e = g_sel[2 * t + slot];
        int p = atomicAdd(&g_cursors[e], 1);
        g_row_token[p] = t;
        g_pos_of[2 * t + slot] = p;
    }
}

// ------------------------------ GEMM ----------------------------------------
// 128x128x16 fp32 tile, 256 threads, 8x8 microtile split 4+4 for conflict-free
// shared reads. GATHER: A rows indirected through g_row_token.
template <int N, int K, bool GATHER, bool RELU>
__global__ void __launch_bounds__(256) k_gemm(const float* __restrict__ A,
                                              const float* __restrict__ Bw,
                                              const float* __restrict__ bias,
                                              float* __restrict__ C) {
    constexpr int BK = 16, BN = 128;
    int tile = blockIdx.x;
    if (tile >= g_n_tiles) return;
    int e    = g_tile_expert[tile];
    int row0 = tile * BM;
    int n0   = blockIdx.y * BN;
    const float* B  = Bw + (size_t)e * K * N + n0;
    const float* bi = bias + (size_t)e * N + n0;

    __shared__ float As[BK][BM];
    __shared__ float Bs[BK][BN];

    int tid = threadIdx.x;
    int tx = tid & 15, ty = tid >> 4;

    const float* aptr[2];
#pragma unroll
    for (int j = 0; j < 2; j++) {
        int r = row0 + (tid >> 2) + j * 64;
        if (GATHER) {
            int tok = g_row_token[r];
            aptr[j] = (tok >= 0) ? A + (size_t)tok * K : nullptr;
        } else {
            aptr[j] = A + (size_t)r * K;
        }
    }
    int akk = (tid & 3) * 4;
    int bkk = tid >> 5;
    int bnn = (tid & 31) * 4;

    float acc[8][8];
#pragma unroll
    for (int i = 0; i < 8; i++)
#pragma unroll
        for (int j = 0; j < 8; j++) acc[i][j] = 0.f;

    for (int k0 = 0; k0 < K; k0 += BK) {
#pragma unroll
        for (int j = 0; j < 2; j++) {
            float4 v = make_float4(0.f, 0.f, 0.f, 0.f);
            if (aptr[j]) v = *reinterpret_cast<const float4*>(aptr[j] + k0 + akk);
            int row = (tid >> 2) + j * 64;
            As[akk + 0][row] = v.x; As[akk + 1][row] = v.y;
            As[akk + 2][row] = v.z; As[akk + 3][row] = v.w;
        }
#pragma unroll
        for (int j = 0; j < 2; j++) {
            int kk = bkk + j * 8;
            *reinterpret_cast<float4*>(&Bs[kk][bnn]) =
                *reinterpret_cast<const float4*>(B + (size_t)(k0 + kk) * N + bnn);
        }
        __syncthreads();
#pragma unroll
        for (int kk = 0; kk < BK; kk++) {
            float ra[8], rb[8];
            *reinterpret_cast<float4*>(ra)     = *reinterpret_cast<float4*>(&As[kk][ty * 4]);
            *reinterpret_cast<float4*>(ra + 4) = *reinterpret_cast<float4*>(&As[kk][64 + ty * 4]);
            *reinterpret_cast<float4*>(rb)     = *reinterpret_cast<float4*>(&Bs[kk][tx * 4]);
            *reinterpret_cast<float4*>(rb + 4) = *reinterpret_cast<float4*>(&Bs[kk][64 + tx * 4]);
#pragma unroll
            for (int i = 0; i < 8; i++)
#pragma unroll
                for (int j = 0; j < 8; j++) acc[i][j] = fmaf(ra[i], rb[j], acc[i][j]);
        }
        __syncthreads();
    }

    float bv[8];
    *reinterpret_cast<float4*>(bv)     = *reinterpret_cast<const float4*>(bi + tx * 4);
    *reinterpret_cast<float4*>(bv + 4) = *reinterpret_cast<const float4*>(bi + 64 + tx * 4);

#pragma unroll
    for (int i = 0; i < 8; i++) {
        int m = (i < 4) ? (ty * 4 + i) : (64 + ty * 4 + (i - 4));
        float* crow = C + (size_t)(row0 + m) * N + n0;
        float o[8];
#pragma unroll
        for (int j = 0; j < 8; j++) {
            float v = acc[i][j] + bv[j];
            if (RELU) v = fmaxf(v, 0.f);
            o[j] = v;
        }
        *reinterpret_cast<float4*>(crow + tx * 4)      = *reinterpret_cast<float4*>(o);
        *reinterpret_cast<float4*>(crow + 64 + tx * 4) = *reinterpret_cast<float4*>(o + 4);
    }
}

// -------------------- combine + residual + LayerNorm ------------------------
__global__ void __launch_bounds__(256) k_combine(const float* __restrict__ x,
                                                 const float* __restrict__ gamma,
                                                 const float* __restrict__ beta,
                                                 float* __restrict__ out) {
    __shared__ float vals[D_IN];
    __shared__ float red[256];
    __shared__ float s_mu, s_rs;
    int t = blockIdx.x;
    int tid = threadIdx.x;

    int   p0 = g_pos_of[2 * t],  p1 = g_pos_of[2 * t + 1];
    float g0 = g_gate[2 * t],    g1 = g_gate[2 * t + 1];
    const float* y0 = g_yb + (size_t)p0 * D_IN;
    const float* y1 = g_yb + (size_t)p1 * D_IN;
    const float* xr = x + (size_t)t * D_IN;

    float s = 0.f;
    for (int d = tid; d < D_IN; d += 256) {
        float v = fmaf(g0, y0[d], fmaf(g1, y1[d], xr[d]));
        vals[d] = v;
        s += v;
    }
    red[tid] = s; __syncthreads();
    for (int off = 128; off; off >>= 1) {
        if (tid < off) red[tid] += red[tid + off];
        __syncthreads();
    }
    if (tid == 0) s_mu = red[0] * (1.f / D_IN);
    __syncthreads();
    float mu = s_mu;

    float s2 = 0.f;
    for (int d = tid; d < D_IN; d += 256) {
        float dv = vals[d] - mu;
        s2 += dv * dv;
    }
    red[tid] = s2; __syncthreads();
    for (int off = 128; off; off >>= 1) {
        if (tid < off) red[tid] += red[tid + off];
        __syncthreads();
    }
    if (tid == 0) s_rs = rsqrtf(red[0] * (1.f / D_IN) + 1e-5f);
    __syncthreads();
    float rs = s_rs;

    float* orow = out + (size_t)t * D_IN;
    for (int d = tid; d < D_IN; d += 256)
        orow[d] = (vals[d] - mu) * rs * gamma[d] + beta[d];
}

// ------------------------------ loss ----------------------------------------
__global__ void k_loss(float* __restrict__ loss_out) {
    __shared__ float simp[NEXP * 256];
    __shared__ float sld[NEXP * 256];
    __shared__ float rimp[NEXP], rld[NEXP];
    int tid = threadIdx.x;

    float imp[NEXP], ld[NEXP];
#pragma unroll
    for (int e = 0; e < NEXP; e++) { imp[e] = 0.f; ld[e] = 0.f; }
    for (int t = tid; t < T_TOK; t += 256) {
#pragma unroll
        for (int slot = 0; slot < 2; slot++) {
            int e = g_sel[2 * t + slot];
            imp[e] += g_gate[2 * t + slot];
            ld[e]  += 1.f;
        }
    }
#pragma unroll
    for (int e = 0; e < NEXP; e++) {
        simp[e * 256 + tid] = imp[e];
        sld[e * 256 + tid]  = ld[e];
    }
    __syncthreads();
    if (tid < NEXP) {
        float si = 0.f, sl = 0.f;
        for (int j = 0; j < 256; j++) { si += simp[tid * 256 + j]; sl += sld[tid * 256 + j]; }
        rimp[tid] = si; rld[tid] = sl;
    }
    __syncthreads();
    if (tid == 0) {
        float mi = 0.f, ml = 0.f;
        for (int e = 0; e < NEXP; e++) { mi += rimp[e]; ml += rld[e]; }
        mi *= (1.f / NEXP); ml *= (1.f / NEXP);
        float vi = 0.f, vl = 0.f;
        for (int e = 0; e < NEXP; e++) {
            float d1 = rimp[e] - mi; vi += d1 * d1;
            float d2 = rld[e]  - ml; vl += d2 * d2;
        }
        vi *= (1.f / NEXP); vl *= (1.f / NEXP);
        *loss_out = vi / (mi * mi + 1e-10f) + vl / (ml * ml + 1e-10f);
    }
}

// ------------------------------ launch --------------------------------------
extern "C" void kernel_launch(void* const* d_in, const int* in_sizes, int n_in,
                              void* d_out, int out_size) {
    const float* x     = (const float*)d_in[0];
    const float* Wg    = (const float*)d_in[1];
    const float* W1    = (const float*)d_in[2];
    const float* b1    = (const float*)d_in[3];
    const float* W2    = (const float*)d_in[4];
    const float* b2    = (const float*)d_in[5];
    const float* gamma = (const float*)d_in[6];
    const float* beta  = (const float*)d_in[7];
    float* out = (float*)d_out;

    k_init<<<(MAX_ROWS + 255) / 256, 256>>>();
    k_gate<<<T_TOK / 8, 256>>>(x, Wg);
    k_scan<<<1, 1>>>();
    k_scatter<<<(T_TOK + 255) / 256, 256>>>();

    float* h_buf; cudaGetSymbolAddress((void**)&h_buf, g_h);
    float* y_buf; cudaGetSymbolAddress((void**)&y_buf, g_yb);

    // GEMM1: h = relu(x_gathered @ W1[e] + b1[e])   [rows x 2048]
    k_gemm<D_HID, D_IN, true, true>
        <<<dim3(MAX_TILES, D_HID / 128), 256>>>(x, W1, b1, h_buf);
    // GEMM2: y = h @ W2[e] + b2[e]                  [rows x 1024]
    k_gemm<D_IN, D_HID, false, false>
        <<<dim3(MAX_TILES, D_IN / 128), 256>>>(h_buf, W2, b2, y_buf);

    k_combine<<<T_TOK, 256>>>(x, gamma, beta, out);
    k_loss<<<1, 256>>>(out + (out_size - 1));
}

// round 4
// speedup vs baseline: 2.1846x; 2.1846x over previous
#include <cuda_runtime.h>
#include <math.h>
#include <stdint.h>

// ---------------------------------------------------------------------------
// MoE FFN + residual + LayerNorm. mma.sync tf32 GEMMs (compute_100-safe).
// T=8192 tokens, D=1024, H=2048, E=8 experts, top-2.
// ---------------------------------------------------------------------------

constexpr int T_TOK = 8192;
constexpr int D_IN  = 1024;
constexpr int D_HID = 2048;
constexpr int NEXP  = 8;

constexpr int BM = 128;
constexpr int MAX_ROWS  = T_TOK * 2 + NEXP * BM; // 17408
constexpr int MAX_TILES = MAX_ROWS / BM;         // 136

// ------------------------- device scratch (static) -------------------------
__device__ float g_h  [(size_t)MAX_ROWS * D_HID];
__device__ float g_yb [(size_t)MAX_ROWS * D_IN];
__device__ int   g_row_token[MAX_ROWS];
__device__ int   g_pos_of[T_TOK * 2];
__device__ int   g_sel[T_TOK * 2];
__device__ float g_gate[T_TOK * 2];
__device__ int   g_counts[NEXP];
__device__ int   g_cursors[NEXP];
__device__ int   g_tile_expert[MAX_TILES];
__device__ int   g_n_tiles;

// --------------------------- PTX helpers -----------------------------------
__device__ __forceinline__ uint32_t smem_u32(const void* p) {
    uint32_t a;
    asm("{ .reg .u64 t; cvta.to.shared.u64 t, %1; cvt.u32.u64 %0, t; }"
        : "=r"(a) : "l"(p));
    return a;
}
__device__ __forceinline__ uint32_t cvt_tf32(float f) {
    uint32_t r;
    asm("cvt.rna.tf32.f32 %0, %1;" : "=r"(r) : "f"(f));
    return r;
}
__device__ __forceinline__ void mma_m16n8k8(float* c, const uint32_t* a,
                                            const uint32_t* b) {
    asm volatile(
        "mma.sync.aligned.m16n8k8.row.col.f32.tf32.tf32.f32 "
        "{%0,%1,%2,%3}, {%4,%5,%6,%7}, {%8,%9}, {%0,%1,%2,%3};"
        : "+f"(c[0]), "+f"(c[1]), "+f"(c[2]), "+f"(c[3])
        : "r"(a[0]), "r"(a[1]), "r"(a[2]), "r"(a[3]), "r"(b[0]), "r"(b[1]));
}
__device__ __forceinline__ void cp16(uint32_t dst, const float* src, uint32_t sz) {
    asm volatile("cp.async.cg.shared.global [%0], [%1], 16, %2;"
                 :: "r"(dst), "l"(src), "r"(sz));
}
#define CP_COMMIT() asm volatile("cp.async.commit_group;" ::: "memory")
template <int N>
__device__ __forceinline__ void cp_wait() {
    asm volatile("cp.async.wait_group %0;" :: "n"(N) : "memory");
}

// ------------------------------ init --------------------------------------
__global__ void k_init() {
    int i = blockIdx.x * blockDim.x + threadIdx.x;
    if (i < MAX_ROWS) g_row_token[i] = -1;
    if (i < NEXP) g_counts[i] = 0;
}

// ------------------------------ gating (fp32, exact) ------------------------
__global__ void k_gate(const float* __restrict__ x, const float* __restrict__ Wg) {
    int warp = threadIdx.x >> 5;
    int lane = threadIdx.x & 31;
    int t = blockIdx.x * 8 + warp;
    if (t >= T_TOK) return;
    const float* xr = x + (size_t)t * D_IN;
    const float4* wg4 = reinterpret_cast<const float4*>(Wg);

    float acc[8];
#pragma unroll
    for (int j = 0; j < 8; j++) acc[j] = 0.f;
    for (int i = lane; i < D_IN; i += 32) {
        float xv = xr[i];
        float4 a = wg4[i * 2];
        float4 b = wg4[i * 2 + 1];
        acc[0] += xv * a.x; acc[1] += xv * a.y; acc[2] += xv * a.z; acc[3] += xv * a.w;
        acc[4] += xv * b.x; acc[5] += xv * b.y; acc[6] += xv * b.z; acc[7] += xv * b.w;
    }
#pragma unroll
    for (int j = 0; j < 8; j++) {
#pragma unroll
        for (int off = 16; off; off >>= 1)
            acc[j] += __shfl_down_sync(0xffffffff, acc[j], off);
    }
    if (lane == 0) {
        int i0 = 0; float v0 = acc[0];
#pragma unroll
        for (int e = 1; e < 8; e++) if (acc[e] > v0) { v0 = acc[e]; i0 = e; }
        int i1 = -1; float v1 = -3.4e38f;
#pragma unroll
        for (int e = 0; e < 8; e++)
            if (e != i0 && acc[e] > v1) { v1 = acc[e]; i1 = e; }
        float e1 = expf(v1 - v0);
        float inv = 1.f / (1.f + e1);
        g_sel[2 * t] = i0;  g_sel[2 * t + 1] = i1;
        g_gate[2 * t] = inv; g_gate[2 * t + 1] = e1 * inv;
        atomicAdd(&g_counts[i0], 1);
        atomicAdd(&g_counts[i1], 1);
    }
}

// ------------------------------ scan / scatter ------------------------------
__global__ void k_scan() {
    int total_tiles = 0, pos = 0;
    for (int e = 0; e < NEXP; e++) {
        g_cursors[e] = pos;
        int nt = (g_counts[e] + BM - 1) / BM;
        for (int j = 0; j < nt; j++) g_tile_expert[total_tiles + j] = e;
        total_tiles += nt;
        pos += nt * BM;
    }
    g_n_tiles = total_tiles;
}
__global__ void k_scatter() {
    int t = blockIdx.x * blockDim.x + threadIdx.x;
    if (t >= T_TOK) return;
#pragma unroll
    for (int slot = 0; slot < 2; slot++) {
        int e = g_sel[2 * t + slot];
        int p = atomicAdd(&g_cursors[e], 1);
        g_row_token[p] = t;
        g_pos_of[2 * t + slot] = p;
    }
}

// ------------------------------ mma.sync tf32 GEMM --------------------------
// C[128 x 128] = A[128 x K] @ B[K x 128] (+bias, opt relu)
// As padded [128][36] (pad%32==4 -> conflict-free a-frags)
// Bs padded  [32][136] (pad%32==8 -> conflict-free b-frags)
constexpr int AS_STRIDE = 36;
constexpr int BS_STRIDE = 136;
constexpr int AS_FLOATS = 128 * AS_STRIDE;     // 4608
constexpr int BS_FLOATS = 32 * BS_STRIDE;      // 4352
constexpr int OFF_AS0 = 0;
constexpr int OFF_AS1 = AS_FLOATS;
constexpr int OFF_BS0 = 2 * AS_FLOATS;                 // 9216
constexpr int OFF_BS1 = 2 * AS_FLOATS + BS_FLOATS;     // 13568
constexpr int OFF_BIAS = 2 * AS_FLOATS + 2 * BS_FLOATS;// 17920
constexpr int SMEM_FLOATS = OFF_BIAS + 128;            // 18048
constexpr int SMEM_BYTES = SMEM_FLOATS * 4;            // 72192

template <int NTOT, int K, bool GATHER, bool RELU>
__global__ void __launch_bounds__(256, 2) k_gemm_mma(const float* __restrict__ A,
                                                     const float* __restrict__ Bg,
                                                     const float* __restrict__ bias,
                                                     float* __restrict__ C) {
    extern __shared__ float sm[];
    int tile = blockIdx.x;
    if (tile >= g_n_tiles) return;
    int e    = g_tile_expert[tile];
    int row0 = tile * BM;
    int n0   = blockIdx.y * 128;
    int tid  = threadIdx.x;
    int lane = tid & 31, wid = tid >> 5;
    int g = lane >> 2, t = lane & 3;
    int m_off = (wid & 3) * 32;
    int n_off = (wid >> 2) * 64;

    float* sbias = sm + OFF_BIAS;
    if (tid < 128) sbias[tid] = bias[(size_t)e * NTOT + n0 + tid];

    // A: thread loads 16 floats of row (tid>>1), half (tid&1)
    int arow = tid >> 1, ahalf = tid & 1;
    const float* asrc; uint32_t avalid = 16u;
    if (GATHER) {
        int tok = g_row_token[row0 + arow];
        avalid = (tok >= 0) ? 16u : 0u;
        asrc = A + (size_t)(tok < 0 ? 0 : tok) * K + ahalf * 16;
    } else {
        asrc = A + (size_t)(row0 + arow) * K + ahalf * 16;
    }
    // B: thread loads 16 floats of k-row (tid>>3), seg (tid&7)
    int brow = tid >> 3, bseg = tid & 7;
    const float* bsrc = Bg + (size_t)e * K * NTOT + (size_t)brow * NTOT + n0 + bseg * 16;

    uint32_t sa[2], sb[2];
    sa[0] = smem_u32(sm + OFF_AS0 + arow * AS_STRIDE + ahalf * 16);
    sa[1] = smem_u32(sm + OFF_AS1 + arow * AS_STRIDE + ahalf * 16);
    sb[0] = smem_u32(sm + OFF_BS0 + brow * BS_STRIDE + bseg * 16);
    sb[1] = smem_u32(sm + OFF_BS1 + brow * BS_STRIDE + bseg * 16);

    auto load_chunk = [&](int i, int s) {
        int k0 = i * 32;
        const float* ap = asrc + k0;
#pragma unroll
        for (int j = 0; j < 4; j++) cp16(sa[s] + j * 16, ap + j * 4, avalid);
        const float* bp = bsrc + (size_t)k0 * NTOT;
#pragma unroll
        for (int j = 0; j < 4; j++) cp16(sb[s] + j * 16, bp + j * 4, 16u);
        CP_COMMIT();
    };

    float acc[2][8][4];
#pragma unroll
    for (int mt = 0; mt < 2; mt++)
#pragma unroll
        for (int nt = 0; nt < 8; nt++)
#pragma unroll
            for (int q = 0; q < 4; q++) acc[mt][nt][q] = 0.f;

    load_chunk(0, 0);
    load_chunk(1, 1);

    constexpr int NK = K / 32;
    for (int i = 0; i < NK; i++) {
        int s = i & 1;
        if (i + 1 < NK) cp_wait<1>(); else cp_wait<0>();
        __syncthreads();
        const float* As_ = sm + (s ? OFF_AS1 : OFF_AS0);
        const float* Bs_ = sm + (s ? OFF_BS1 : OFF_BS0);
#pragma unroll
        for (int ks = 0; ks < 4; ks++) {
            uint32_t a[2][4], b[8][2];
#pragma unroll
            for (int mt = 0; mt < 2; mt++) {
                const float* p = As_ + (m_off + mt * 16 + g) * AS_STRIDE + ks * 8 + t;
                a[mt][0] = cvt_tf32(p[0]);
                a[mt][1] = cvt_tf32(p[8 * AS_STRIDE]);
                a[mt][2] = cvt_tf32(p[4]);
                a[mt][3] = cvt_tf32(p[8 * AS_STRIDE + 4]);
            }
#pragma unroll
            for (int nt = 0; nt < 8; nt++) {
                const float* p = Bs_ + (ks * 8 + t) * BS_STRIDE + n_off + nt * 8 + g;
                b[nt][0] = cvt_tf32(p[0]);
                b[nt][1] = cvt_tf32(p[4 * BS_STRIDE]);
            }
#pragma unroll
            for (int mt = 0; mt < 2; mt++)
#pragma unroll
                for (int nt = 0; nt < 8; nt++)
                    mma_m16n8k8(acc[mt][nt], a[mt], b[nt]);
        }
        __syncthreads();
        if (i + 2 < NK) load_chunk(i + 2, s);
    }

    // epilogue
#pragma unroll
    for (int mt = 0; mt < 2; mt++) {
        int r0 = row0 + m_off + mt * 16 + g;
        float* c0 = C + (size_t)r0 * NTOT + n0;
        float* c1 = c0 + (size_t)8 * NTOT;
#pragma unroll
        for (int nt = 0; nt < 8; nt++) {
            int col = n_off + nt * 8 + t * 2;
            float2 v0, v1;
            v0.x = acc[mt][nt][0] + sbias[col];
            v0.y = acc[mt][nt][1] + sbias[col + 1];
            v1.x = acc[mt][nt][2] + sbias[col];
            v1.y = acc[mt][nt][3] + sbias[col + 1];
            if (RELU) {
                v0.x = fmaxf(v0.x, 0.f); v0.y = fmaxf(v0.y, 0.f);
                v1.x = fmaxf(v1.x, 0.f); v1.y = fmaxf(v1.y, 0.f);
            }
            *reinterpret_cast<float2*>(c0 + col) = v0;
            *reinterpret_cast<float2*>(c1 + col) = v1;
        }
    }
}

// -------------------- combine + residual + LayerNorm ------------------------
__global__ void __launch_bounds__(256) k_combine(const float* __restrict__ x,
                                                 const float* __restrict__ gamma,
                                                 const float* __restrict__ beta,
                                                 float* __restrict__ out) {
    __shared__ float vals[D_IN];
    __shared__ float red[256];
    __shared__ float s_mu, s_rs;
    int t = blockIdx.x;
    int tid = threadIdx.x;

    int   p0 = g_pos_of[2 * t],  p1 = g_pos_of[2 * t + 1];
    float g0 = g_gate[2 * t],    g1 = g_gate[2 * t + 1];
    const float* y0 = g_yb + (size_t)p0 * D_IN;
    const float* y1 = g_yb + (size_t)p1 * D_IN;
    const float* xr = x + (size_t)t * D_IN;

    float s = 0.f;
    for (int d = tid; d < D_IN; d += 256) {
        float v = fmaf(g0, y0[d], fmaf(g1, y1[d], xr[d]));
        vals[d] = v;
        s += v;
    }
    red[tid] = s; __syncthreads();
    for (int off = 128; off; off >>= 1) {
        if (tid < off) red[tid] += red[tid + off];
        __syncthreads();
    }
    if (tid == 0) s_mu = red[0] * (1.f / D_IN);
    __syncthreads();
    float mu = s_mu;

    float s2 = 0.f;
    for (int d = tid; d < D_IN; d += 256) {
        float dv = vals[d] - mu;
        s2 += dv * dv;
    }
    red[tid] = s2; __syncthreads();
    for (int off = 128; off; off >>= 1) {
        if (tid < off) red[tid] += red[tid + off];
        __syncthreads();
    }
    if (tid == 0) s_rs = rsqrtf(red[0] * (1.f / D_IN) + 1e-5f);
    __syncthreads();
    float rs = s_rs;

    float* orow = out + (size_t)t * D_IN;
    for (int d = tid; d < D_IN; d += 256)
        orow[d] = (vals[d] - mu) * rs * gamma[d] + beta[d];
}

// ------------------------------ loss ----------------------------------------
__global__ void k_loss(float* __restrict__ loss_out) {
    __shared__ float simp[NEXP * 256];
    __shared__ float sld[NEXP * 256];
    __shared__ float rimp[NEXP], rld[NEXP];
    int tid = threadIdx.x;

    float imp[NEXP], ld[NEXP];
#pragma unroll
    for (int e = 0; e < NEXP; e++) { imp[e] = 0.f; ld[e] = 0.f; }
    for (int t = tid; t < T_TOK; t += 256) {
#pragma unroll
        for (int slot = 0; slot < 2; slot++) {
            int e = g_sel[2 * t + slot];
            imp[e] += g_gate[2 * t + slot];
            ld[e]  += 1.f;
        }
    }
#pragma unroll
    for (int e = 0; e < NEXP; e++) {
        simp[e * 256 + tid] = imp[e];
        sld[e * 256 + tid]  = ld[e];
    }
    __syncthreads();
    if (tid < NEXP) {
        float si = 0.f, sl = 0.f;
        for (int j = 0; j < 256; j++) { si += simp[tid * 256 + j]; sl += sld[tid * 256 + j]; }
        rimp[tid] = si; rld[tid] = sl;
    }
    __syncthreads();
    if (tid == 0) {
        float mi = 0.f, ml = 0.f;
        for (int e = 0; e < NEXP; e++) { mi += rimp[e]; ml += rld[e]; }
        mi *= (1.f / NEXP); ml *= (1.f / NEXP);
        float vi = 0.f, vl = 0.f;
        for (int e = 0; e < NEXP; e++) {
            float d1 = rimp[e] - mi; vi += d1 * d1;
            float d2 = rld[e]  - ml; vl += d2 * d2;
        }
        vi *= (1.f / NEXP); vl *= (1.f / NEXP);
        *loss_out = vi / (mi * mi + 1e-10f) + vl / (ml * ml + 1e-10f);
    }
}

// ------------------------------ launch --------------------------------------
extern "C" void kernel_launch(void* const* d_in, const int* in_sizes, int n_in,
                              void* d_out, int out_size) {
    const float* x     = (const float*)d_in[0];
    const float* Wg    = (const float*)d_in[1];
    const float* W1    = (const float*)d_in[2];
    const float* b1    = (const float*)d_in[3];
    const float* W2    = (const float*)d_in[4];
    const float* b2    = (const float*)d_in[5];
    const float* gamma = (const float*)d_in[6];
    const float* beta  = (const float*)d_in[7];
    float* out = (float*)d_out;

    float* h_buf;  cudaGetSymbolAddress((void**)&h_buf,  g_h);
    float* y_buf;  cudaGetSymbolAddress((void**)&y_buf,  g_yb);

    cudaFuncSetAttribute(k_gemm_mma<D_HID, D_IN, true, true>,
                         cudaFuncAttributeMaxDynamicSharedMemorySize, SMEM_BYTES);
    cudaFuncSetAttribute(k_gemm_mma<D_IN, D_HID, false, false>,
                         cudaFuncAttributeMaxDynamicSharedMemorySize, SMEM_BYTES);

    k_init<<<(MAX_ROWS + 255) / 256, 256>>>();
    k_gate<<<T_TOK / 8, 256>>>(x, Wg);
    k_scan<<<1, 1>>>();
    k_scatter<<<(T_TOK + 255) / 256, 256>>>();

    // GEMM1: h = relu(x_gathered @ W1[e] + b1[e])   [rows x 2048]
    k_gemm_mma<D_HID, D_IN, true, true>
        <<<dim3(MAX_TILES, D_HID / 128), 256, SMEM_BYTES>>>(x, W1, b1, h_buf);
    // GEMM2: y = h @ W2[e] + b2[e]                  [rows x 1024]
    k_gemm_mma<D_IN, D_HID, false, false>
        <<<dim3(MAX_TILES, D_IN / 128), 256, SMEM_BYTES>>>(h_buf, W2, b2, y_buf);

    k_combine<<<T_TOK, 256>>>(x, gamma, beta, out);
    k_loss<<<1, 256>>>(out + (out_size - 1));
}